// round 1
// baseline (speedup 1.0000x reference)
#include <cuda_runtime.h>
#include <cuda_bf16.h>

#define BATCH 32
#define NPT 256          // problem size n, also threads per block
#define INF_F 1e9f

// order-preserving float->uint encoding (monotone: a<b  <=>  enc(a)<enc(b))
__device__ __forceinline__ unsigned int ford(float f) {
    unsigned int u = __float_as_uint(f);
    return (u & 0x80000000u) ? ~u : (u | 0x80000000u);
}
__device__ __forceinline__ float forddec(unsigned int e) {
    unsigned int b = (e & 0x80000000u) ? (e ^ 0x80000000u) : ~e;
    return __uint_as_float(b);
}

__global__ void __launch_bounds__(NPT, 1)
hungarian_kernel(const float* __restrict__ pred,
                 const float* __restrict__ gt,
                 float* __restrict__ out,
                 int write_totals)
{
    const int b = blockIdx.x;
    const int t = threadIdx.x;       // 0..255
    const int c = t + 1;             // this thread's column, 1-based

    __shared__ float u_sh[NPT + 1];
    __shared__ int   p_sh[NPT + 1];      // p[j] = row matched to col j (1-based), 0 = free
    __shared__ int   way_sh[NPT + 1];
    __shared__ float pred_sh[NPT * 4];
    __shared__ unsigned long long warp_red[8];
    __shared__ unsigned long long best_sh;
    __shared__ float wsum[8];

    // per-thread gt point (column c-1)
    const float g0 = gt[((size_t)b * NPT + t) * 4 + 0];
    const float g1 = gt[((size_t)b * NPT + t) * 4 + 1];
    const float g2 = gt[((size_t)b * NPT + t) * 4 + 2];
    const float g3 = gt[((size_t)b * NPT + t) * 4 + 3];

    // stage pred rows in smem
    for (int k = t; k < NPT * 4; k += NPT)
        pred_sh[k] = pred[(size_t)b * NPT * 4 + k];

    u_sh[t] = 0.0f;
    p_sh[t] = 0;
    if (t == 0) { u_sh[NPT] = 0.0f; p_sh[NPT] = 0; }
    float v_c = 0.0f;                 // v for this column (only owner reads it)
    __syncthreads();

    for (int i = 1; i <= NPT; ++i) {
        int   j0     = 0;
        float minv_c = INF_F;
        bool  used_c = false;
        if (t == 0) p_sh[0] = i;
        __syncthreads();

        while (true) {
            // mark j0 used (column 0 handled implicitly: u[i] bumped by t==0 below)
            if (c == j0) used_c = true;
            const int   i0  = p_sh[j0];
            const float ui0 = u_sh[i0];

            // reduced cost for this column under current row i0
            float cur;
            {
                const float* pr = &pred_sh[(i0 - 1) * 4];
                float d0 = pr[0] - g0, d1 = pr[1] - g1, d2 = pr[2] - g2, d3 = pr[3] - g3;
                cur = sqrtf(d0 * d0 + d1 * d1 + d2 * d2 + d3 * d3) - ui0 - v_c;
            }
            if (used_c) cur = INF_F;
            if (cur < minv_c) { minv_c = cur; way_sh[c] = j0; }
            const float masked = used_c ? INF_F : minv_c;

            // block argmin with first-index tie-break (matches jnp.argmin)
            unsigned long long key =
                (((unsigned long long)ford(masked)) << 32) | (unsigned int)c;
            #pragma unroll
            for (int off = 16; off; off >>= 1) {
                unsigned long long o = __shfl_xor_sync(0xffffffffu, key, off);
                if (o < key) key = o;
            }
            if ((t & 31) == 0) warp_red[t >> 5] = key;
            __syncthreads();
            if (t == 0) {
                unsigned long long k2 = warp_red[0];
                #pragma unroll
                for (int w = 1; w < 8; ++w)
                    if (warp_red[w] < k2) k2 = warp_red[w];
                best_sh = k2;
            }
            __syncthreads();
            const unsigned long long bk = best_sh;
            const int   j1    = (int)(bk & 0xffffffffu);
            const float delta = forddec((unsigned int)(bk >> 32));

            // dual updates (used columns have pairwise-distinct matched rows -> no conflicts)
            if (used_c) { u_sh[p_sh[c]] += delta; v_c -= delta; }
            else        { minv_c -= delta; }
            if (t == 0) u_sh[i] += delta;   // virtual column 0: p[0]=i, used from 1st iter
            __syncthreads();

            j0 = j1;
            if (p_sh[j1] == 0) break;       // reached a free column
        }

        // augment along the alternating path (serial, thread 0)
        if (t == 0) {
            int j = j0;
            while (j) {
                int jn = way_sh[j];
                p_sh[j] = p_sh[jn];
                j = jn;
            }
        }
        __syncthreads();
    }

    // epilogue: col4row[p[c]-1] = c-1 ; total = sum of matched costs
    const int r = p_sh[c] - 1;           // row matched to this column
    const float* pr = &pred_sh[r * 4];
    float d0 = pr[0] - g0, d1 = pr[1] - g1, d2 = pr[2] - g2, d3 = pr[3] - g3;
    float mc = sqrtf(d0 * d0 + d1 * d1 + d2 * d2 + d3 * d3);

    out[(size_t)b * NPT + r] = (float)t;  // col4row as exact small float

    if (write_totals) {
        #pragma unroll
        for (int off = 16; off; off >>= 1)
            mc += __shfl_xor_sync(0xffffffffu, mc, off);
        if ((t & 31) == 0) wsum[t >> 5] = mc;
        __syncthreads();
        if (t == 0) {
            float s = 0.0f;
            #pragma unroll
            for (int w = 0; w < 8; ++w) s += wsum[w];
            out[(size_t)BATCH * NPT + b] = s;
        }
    }
}

extern "C" void kernel_launch(void* const* d_in, const int* in_sizes, int n_in,
                              void* d_out, int out_size)
{
    const float* pred = (const float*)d_in[0];
    const float* gt   = (const float*)d_in[1];
    float* out        = (float*)d_out;
    int write_totals  = (out_size >= BATCH * NPT + BATCH) ? 1 : 0;
    hungarian_kernel<<<BATCH, NPT>>>(pred, gt, out, write_totals);
}